// round 5
// baseline (speedup 1.0000x reference)
#include <cuda_runtime.h>
#include <cuda_bf16.h>

// EMA: y[n] = w*x[n] + (1-w)*y[n-1], scan over last (contiguous) axis.
// Shapes: input (16,8,256,2048) f32, initial_state (16,8,256), weight (8,256).
// One warp per series (32768 series), 16 chunks of 128 elements.
// R3: constant-decay scan — since every lane shares the same per-element decay,
// the Kogge-Stone A-component is a precomputed constant omw^(4d) per step, so
// only B is scanned: 5 SHFL + 5 FMA (vs 10 SHFL affine-pair scan). Depth-2
// prefetch with a register cap keeps occupancy at R1 levels.

#define N_FRAMES 2048
#define SERIES_PER_WB 2048   /* N_RES * N_BINS = 8*256 */
#define N_SERIES 32768       /* 16*8*256 */

__global__ __launch_bounds__(256, 6)
void ema_scan_kernel(const float* __restrict__ x,
                     const float* __restrict__ init_state,
                     const float* __restrict__ weight,
                     float* __restrict__ y) {
    const int warp_global = (blockIdx.x * blockDim.x + threadIdx.x) >> 5;
    const int lane = threadIdx.x & 31;
    if (warp_global >= N_SERIES) return;

    const int series = warp_global;

    // weight index = series % (N_RES*N_BINS); clamp to [0,1]
    const float w_raw = weight[series & (SERIES_PER_WB - 1)];
    const float w   = fminf(fmaxf(w_raw, 0.0f), 1.0f);
    const float omw = 1.0f - w;

    // Powers of the 4-element decay: P[k] = omw^(4*2^k)
    const float P1  = ((omw * omw) * (omw * omw));  // omw^4
    const float P2  = P1 * P1;                      // omw^8
    const float P4  = P2 * P2;                      // omw^16
    const float P8  = P4 * P4;                      // omw^32
    const float P16 = P8 * P8;                      // omw^64

    // Apow = omw^(4*lane): multiplier applied to the incoming carry for this
    // lane's exclusive state. lane 0 -> 1.0.
    float Apow = 1.0f;
    if (lane & 1)  Apow *= P1;
    if (lane & 2)  Apow *= P2;
    if (lane & 4)  Apow *= P4;
    if (lane & 8)  Apow *= P8;
    if (lane & 16) Apow *= P16;

    float carry = init_state[series];

    const float4* __restrict__ xin  =
        reinterpret_cast<const float4*>(x + (size_t)series * N_FRAMES);
    float4* __restrict__ yout =
        reinterpret_cast<float4*>(y + (size_t)series * N_FRAMES);

    // Depth-2 software pipeline: chunk it+1 loads while chunk it scans.
    float4 v = __ldcs(&xin[lane]);

    #pragma unroll
    for (int it = 0; it < N_FRAMES / 128; ++it) {
        float4 nv;
        if (it < N_FRAMES / 128 - 1)
            nv = __ldcs(&xin[(it + 1) * 32 + lane]);

        // Local composite: B = EMA of this lane's 4 x's starting from 0.
        float B = w * v.x;
        B = fmaf(omw, B, w * v.y);
        B = fmaf(omw, B, w * v.z);
        B = fmaf(omw, B, w * v.w);

        // B-only Kogge-Stone scan with constant segment multipliers.
        float Bu;
        Bu = __shfl_up_sync(0xFFFFFFFFu, B, 1);
        if (lane >= 1)  B = fmaf(P1,  Bu, B);
        Bu = __shfl_up_sync(0xFFFFFFFFu, B, 2);
        if (lane >= 2)  B = fmaf(P2,  Bu, B);
        Bu = __shfl_up_sync(0xFFFFFFFFu, B, 4);
        if (lane >= 4)  B = fmaf(P4,  Bu, B);
        Bu = __shfl_up_sync(0xFFFFFFFFu, B, 8);
        if (lane >= 8)  B = fmaf(P8,  Bu, B);
        Bu = __shfl_up_sync(0xFFFFFFFFu, B, 16);
        if (lane >= 16) B = fmaf(P16, Bu, B);

        // Exclusive incoming state: y_in = omw^(4*lane)*carry + B[lane-1].
        float Be = __shfl_up_sync(0xFFFFFFFFu, B, 1);
        float y_in = fmaf(Apow, carry, (lane == 0) ? 0.0f : Be);

        // Reproduce the exact sequential per-element recurrence locally.
        float y0 = fmaf(omw, y_in, w * v.x);
        float y1 = fmaf(omw, y0,  w * v.y);
        float y2 = fmaf(omw, y1,  w * v.z);
        float y3 = fmaf(omw, y2,  w * v.w);

        __stcs(&yout[it * 32 + lane], make_float4(y0, y1, y2, y3));

        // Carry = lane 31's final value.
        carry = __shfl_sync(0xFFFFFFFFu, y3, 31);
        v = nv;
    }
}

extern "C" void kernel_launch(void* const* d_in, const int* in_sizes, int n_in,
                              void* d_out, int out_size) {
    const float* x    = (const float*)d_in[0];   // input (16,8,256,2048)
    const float* init = (const float*)d_in[1];   // initial_state (16,8,256)
    const float* wgt  = (const float*)d_in[2];   // weight (8,256)
    float* y = (float*)d_out;

    // 32768 warps, 8 warps (256 threads) per block -> 4096 blocks.
    const int threads = 256;
    const int blocks = (N_SERIES * 32) / threads;
    ema_scan_kernel<<<blocks, threads>>>(x, init, wgt, y);
}